// round 2
// baseline (speedup 1.0000x reference)
#include <cuda_runtime.h>
#include <math.h>
#include <stdint.h>

// ---------------- problem constants ----------------
#define D_MODEL 1024
#define KOSC    256
#define BATCH   4
#define SEQ     4096
#define M_TOT   (BATCH*SEQ)      // 16384
#define NPROJ   (6*KOSC)         // 1536
#define NRHO    1024             // 4K-2 = 1022, padded to 1024
#define TILE_N  128              // scan tile length along n
#define NTILES  (SEQ/TILE_N)     // 32

// ---------------- scratch (static device globals; no runtime alloc) ------
__device__ float g_proj[(size_t)M_TOT * NPROJ];   // 96 MB
__device__ float g_pq  [(size_t)M_TOT * KOSC];    // 16 MB
__device__ float g_rho [(size_t)M_TOT * NRHO];    // 64 MB
__device__ float g_Wpad[1024 * 1024];             // 4 MB, W_res repacked ld=1024
__device__ float g_tA [BATCH*NTILES*KOSC];
__device__ float g_tBr[BATCH*NTILES*KOSC];
__device__ float g_tBi[BATCH*NTILES*KOSC];
__device__ float g_pR [BATCH*NTILES*KOSC];
__device__ float g_pI [BATCH*NTILES*KOSC];

// ---------------- helpers ----------------
__device__ __forceinline__ float sigmoidf_(float x) { return 1.0f / (1.0f + expf(-x)); }
__device__ __forceinline__ float softplusf_(float x) {
    // logaddexp(x, 0) = max(x,0) + log1p(exp(-|x|))   (matches jax.nn.softplus)
    return fmaxf(x, 0.0f) + log1pf(expf(-fabsf(x)));
}

// ---------------- SGEMM (NT): C[M,N] = scale * (A[M,K] * B[N,K]^T + bias[N]) ----------------
#define BM 128
#define BN 128
#define BK 16
#define TM 8
#define TN 8

__global__ __launch_bounds__(256)
void sgemm_nt(const float* __restrict__ A, const float* __restrict__ B,
              float* __restrict__ C, const float* __restrict__ bias,
              const float* __restrict__ scale_ptr,
              int M, int N, int Kd)
{
    __shared__ float As[BK][BM + 4];
    __shared__ float Bs[BK][BN + 4];

    const int tid = threadIdx.x;
    const int m0 = blockIdx.y * BM;
    const int n0 = blockIdx.x * BN;
    const int tr = tid >> 4;          // 0..15
    const int tc = tid & 15;          // 0..15

    float acc[TM][TN];
    #pragma unroll
    for (int i = 0; i < TM; i++)
        #pragma unroll
        for (int j = 0; j < TN; j++) acc[i][j] = 0.0f;

    for (int k0 = 0; k0 < Kd; k0 += BK) {
        // load BMxBK A-tile and BNxBK B-tile, transposed into smem
        #pragma unroll
        for (int l = 0; l < 2; l++) {
            int f   = tid + l * 256;      // float4 index 0..511
            int row = f >> 2;             // 0..127
            int c4  = f & 3;              // 0..3
            float4 va = *reinterpret_cast<const float4*>(
                &A[(size_t)(m0 + row) * Kd + k0 + c4 * 4]);
            As[c4*4+0][row] = va.x; As[c4*4+1][row] = va.y;
            As[c4*4+2][row] = va.z; As[c4*4+3][row] = va.w;
            float4 vb = *reinterpret_cast<const float4*>(
                &B[(size_t)(n0 + row) * Kd + k0 + c4 * 4]);
            Bs[c4*4+0][row] = vb.x; Bs[c4*4+1][row] = vb.y;
            Bs[c4*4+2][row] = vb.z; Bs[c4*4+3][row] = vb.w;
        }
        __syncthreads();

        #pragma unroll
        for (int kk = 0; kk < BK; kk++) {
            float4 a0 = *reinterpret_cast<const float4*>(&As[kk][tr * 8 + 0]);
            float4 a1 = *reinterpret_cast<const float4*>(&As[kk][tr * 8 + 4]);
            float4 b0 = *reinterpret_cast<const float4*>(&Bs[kk][tc * 8 + 0]);
            float4 b1 = *reinterpret_cast<const float4*>(&Bs[kk][tc * 8 + 4]);
            float af[TM] = {a0.x, a0.y, a0.z, a0.w, a1.x, a1.y, a1.z, a1.w};
            float bf[TN] = {b0.x, b0.y, b0.z, b0.w, b1.x, b1.y, b1.z, b1.w};
            #pragma unroll
            for (int i = 0; i < TM; i++)
                #pragma unroll
                for (int j = 0; j < TN; j++)
                    acc[i][j] = fmaf(af[i], bf[j], acc[i][j]);
        }
        __syncthreads();
    }

    const float sc = scale_ptr ? *scale_ptr : 1.0f;
    float bv[TN];
    #pragma unroll
    for (int j = 0; j < TN; j++)
        bv[j] = bias ? bias[n0 + tc * 8 + j] : 0.0f;

    #pragma unroll
    for (int i = 0; i < TM; i++) {
        int m = m0 + tr * 8 + i;
        #pragma unroll
        for (int j0 = 0; j0 < TN; j0 += 4) {
            float4 v;
            v.x = sc * (acc[i][j0 + 0] + bv[j0 + 0]);
            v.y = sc * (acc[i][j0 + 1] + bv[j0 + 1]);
            v.z = sc * (acc[i][j0 + 2] + bv[j0 + 2]);
            v.w = sc * (acc[i][j0 + 3] + bv[j0 + 3]);
            *reinterpret_cast<float4*>(&C[(size_t)m * N + n0 + tc * 8 + j0]) = v;
        }
    }
}

// ---------------- W_res repack: (1024,1022) -> (1024,1024 zero-padded) -------
__global__ __launch_bounds__(256)
void repack_wres(const float* __restrict__ W)
{
    int idx = blockIdx.x * 256 + threadIdx.x;    // 0 .. 1024*1024-1
    int d = idx >> 10;
    int k = idx & 1023;
    g_Wpad[idx] = (k < 1022) ? W[(size_t)d * 1022 + k] : 0.0f;
}

// ---------------- scan stage 1: per-tile composition (aP, bR, bI) ------------
__global__ __launch_bounds__(KOSC)
void scan_partial()
{
    const int b = blockIdx.y;
    const int tile = blockIdx.x;
    const int k = threadIdx.x;
    float aP = 1.0f, bR = 0.0f, bI = 0.0f;
    const int nbase = tile * TILE_N;

    for (int i = 0; i < TILE_N; i++) {
        int n = nbase + i;
        size_t base = (size_t)(b * SEQ + n) * NPROJ;
        float a_raw  = g_proj[base + k];
        float w_raw  = g_proj[base + KOSC + k];
        float p_raw  = g_proj[base + 2 * KOSC + k];
        float al_raw = g_proj[base + 3 * KOSC + k];

        float alpha = sigmoidf_(al_raw);
        float Aamp  = 3.0f * sigmoidf_(a_raw);
        float omega = softplusf_(w_raw);
        float lp    = log1pf((float)n);
        float s, c;
        sincosf(fmaf(omega, lp, p_raw), &s, &c);
        float oma = 1.0f - alpha;
        bR = fmaf(alpha, bR, oma * Aamp * c);
        bI = fmaf(alpha, bI, oma * Aamp * s);
        aP *= alpha;
    }
    int idx = (b * NTILES + tile) * KOSC + k;
    g_tA[idx] = aP; g_tBr[idx] = bR; g_tBi[idx] = bI;
}

// ---------------- scan stage 2: sequential combine across tiles --------------
__global__ __launch_bounds__(KOSC)
void scan_prefix()
{
    const int b = blockIdx.x;
    const int k = threadIdx.x;
    float rr = 0.0f, ri = 0.0f;
    for (int t = 0; t < NTILES; t++) {
        int idx = (b * NTILES + t) * KOSC + k;
        g_pR[idx] = rr; g_pI[idx] = ri;
        float a = g_tA[idx];
        rr = fmaf(a, rr, g_tBr[idx]);
        ri = fmaf(a, ri, g_tBi[idx]);
    }
}

// ---------------- scan stage 3: final pass + full elementwise tail -----------
__global__ __launch_bounds__(KOSC)
void scan_final(const float* __restrict__ lambda_ptr)
{
    __shared__ float s_re[KOSC], s_im[KOSC], s_g[KOSC];
    const int b = blockIdx.y;
    const int tile = blockIdx.x;
    const int k = threadIdx.x;
    const float lam = *lambda_ptr;

    int idx = (b * NTILES + tile) * KOSC + k;
    float rr = g_pR[idx], ri = g_pI[idx];
    const int nbase = tile * TILE_N;

    for (int i = 0; i < TILE_N; i++) {
        int n = nbase + i;
        size_t row = (size_t)(b * SEQ + n);
        size_t base = row * NPROJ;
        float a_raw  = g_proj[base + k];
        float w_raw  = g_proj[base + KOSC + k];
        float p_raw  = g_proj[base + 2 * KOSC + k];
        float al_raw = g_proj[base + 3 * KOSC + k];
        float g_raw  = g_proj[base + 4 * KOSC + k];
        float be_raw = g_proj[base + 5 * KOSC + k];

        float alpha = sigmoidf_(al_raw);
        float Aamp  = 3.0f * sigmoidf_(a_raw);
        float omega = softplusf_(w_raw);
        float g     = sigmoidf_(g_raw);
        float beta  = sigmoidf_(be_raw);
        float lp    = log1pf((float)n);
        float s, c;
        sincosf(fmaf(omega, lp, p_raw), &s, &c);

        // scan update (carry state rr/ri is PRE-erase, matching reference)
        float oma = 1.0f - alpha;
        rr = fmaf(alpha, rr, oma * Aamp * c);
        ri = fmaf(alpha, ri, oma * Aamp * s);

        // erase (read-and-subtract)
        float readout = rr * c + ri * s;
        float er = rr - beta * readout * c;
        float ei = ri - beta * readout * s;

        // state norm: r /= max(|r|, 1)
        float mod = sqrtf(er * er + ei * ei + 1e-8f);
        float inv = 1.0f / fmaxf(mod, 1.0f);
        er *= inv; ei *= inv;

        // demodulate
        float re =  er * c + ei * s;
        float im = -er * s + ei * c;

        // phase-coherence gate
        float rn = sqrtf(re * re + im * im + 1e-8f);
        float pq = g_pq[row * KOSC + k];
        float sq, cq;
        sincosf(pq, &sq, &cq);
        float align = (re * cq + im * sq) / rn;
        float gate = sigmoidf_(lam * align);
        re *= gate; im *= gate;

        // SCPM neighbor cross products via smem
        s_re[k] = re; s_im[k] = im; s_g[k] = g;
        __syncthreads();

        size_t ob = row * NRHO;
        g_rho[ob + k]        = g * re;
        g_rho[ob + KOSC + k] = g * im;
        if (k < KOSC - 1) {
            float re2 = s_re[k + 1], im2 = s_im[k + 1], g2 = s_g[k + 1];
            float xr = re * re2 - im * im2;
            float xi = re * im2 + im * re2;
            float gc = 0.5f * (g + g2);
            g_rho[ob + 2 * KOSC + k]              = gc * xr;   // 512..766
            g_rho[ob + 2 * KOSC + (KOSC - 1) + k] = gc * xi;   // 767..1021
        } else {
            g_rho[ob + 1022] = 0.0f;   // pad columns
            g_rho[ob + 1023] = 0.0f;
        }
        __syncthreads();
    }
}

// ---------------- launch ----------------
extern "C" void kernel_launch(void* const* d_in, const int* in_sizes, int n_in,
                              void* d_out, int out_size)
{
    const float* x        = (const float*)d_in[0];   // (4,4096,1024)
    const float* W_proj   = (const float*)d_in[1];   // (1536,1024)
    const float* b_proj   = (const float*)d_in[2];   // (1536,)
    const float* W_res    = (const float*)d_in[3];   // (1024,1022)
    const float* W_phase  = (const float*)d_in[4];   // (256,1024)
    const float* b_phase  = (const float*)d_in[5];   // (256,)
    const float* lambda_p = (const float*)d_in[6];   // scalar
    const float* res_p    = (const float*)d_in[7];   // scalar
    float* out = (float*)d_out;

    float *proj, *pq, *rho, *wpad;
    cudaGetSymbolAddress((void**)&proj, g_proj);
    cudaGetSymbolAddress((void**)&pq,   g_pq);
    cudaGetSymbolAddress((void**)&rho,  g_rho);
    cudaGetSymbolAddress((void**)&wpad, g_Wpad);

    // repack W_res into padded ld=1024 layout
    repack_wres<<<(1024 * 1024) / 256, 256>>>(W_res);

    // GEMM1a: proj = x @ W_proj^T + b_proj   (16384 x 1536 x 1024)
    {
        dim3 grid(NPROJ / BN, M_TOT / BM);
        sgemm_nt<<<grid, 256>>>(x, W_proj, proj, b_proj, nullptr, M_TOT, NPROJ, D_MODEL);
    }
    // GEMM1b: pq = x @ W_phase^T + b_phase   (16384 x 256 x 1024)
    {
        dim3 grid(KOSC / BN, M_TOT / BM);
        sgemm_nt<<<grid, 256>>>(x, W_phase, pq, b_phase, nullptr, M_TOT, KOSC, D_MODEL);
    }

    // scan decomposition
    scan_partial<<<dim3(NTILES, BATCH), KOSC>>>();
    scan_prefix<<<BATCH, KOSC>>>();
    scan_final<<<dim3(NTILES, BATCH), KOSC>>>(lambda_p);

    // GEMM2: out = res_scale * rho_pad @ Wpad^T   (16384 x 1024 x 1024)
    {
        dim3 grid(NRHO / BN, M_TOT / BM);
        sgemm_nt<<<grid, 256>>>(rho, wpad, out, nullptr, res_p, M_TOT, NRHO, NRHO);
    }
}

// round 4
// speedup vs baseline: 2.4387x; 2.4387x over previous
#include <cuda_runtime.h>
#include <cuda_bf16.h>
#include <math.h>
#include <stdint.h>

// ---------------- problem constants ----------------
#define D_MODEL 1024
#define KOSC    256
#define BATCH   4
#define SEQ     4096
#define M_TOT   (BATCH*SEQ)      // 16384
#define NPROJ   (6*KOSC)         // 1536
#define NRHO    1024             // 4K-2 = 1022 padded
#define TILE_N  32
#define NTILES  (SEQ/TILE_N)     // 128

// ---------------- scratch ----------------
__device__ float         g_proj[(size_t)M_TOT * NPROJ];
__device__ float         g_pq  [(size_t)M_TOT * KOSC];
__device__ __nv_bfloat16 g_xhi [(size_t)M_TOT * D_MODEL];
__device__ __nv_bfloat16 g_xlo [(size_t)M_TOT * D_MODEL];
__device__ __nv_bfloat16 g_wph [(size_t)NPROJ * D_MODEL];
__device__ __nv_bfloat16 g_wpl [(size_t)NPROJ * D_MODEL];
__device__ __nv_bfloat16 g_wqh [(size_t)KOSC * D_MODEL];
__device__ __nv_bfloat16 g_wql [(size_t)KOSC * D_MODEL];
__device__ __nv_bfloat16 g_wrh [(size_t)1024 * 1024];
__device__ __nv_bfloat16 g_wrl [(size_t)1024 * 1024];
__device__ __nv_bfloat16 g_rhoh[(size_t)M_TOT * NRHO];
__device__ __nv_bfloat16 g_rhol[(size_t)M_TOT * NRHO];
__device__ float g_tA [BATCH*NTILES*KOSC];
__device__ float g_tBr[BATCH*NTILES*KOSC];
__device__ float g_tBi[BATCH*NTILES*KOSC];
__device__ float g_pR [BATCH*NTILES*KOSC];
__device__ float g_pI [BATCH*NTILES*KOSC];

// ---------------- PTX helpers (family-portable only: sm_80-class) ------------
__device__ __forceinline__ uint32_t smem_u32(const void* p) {
    uint32_t a;
    asm("{ .reg .u64 t; cvta.to.shared.u64 t, %1; cvt.u32.u64 %0, t; }" : "=r"(a) : "l"(p));
    return a;
}
__device__ __forceinline__ void cpasync16(uint32_t s, const void* g) {
    asm volatile("cp.async.cg.shared.global [%0], [%1], 16;" :: "r"(s), "l"(g));
}
#define CP_COMMIT() asm volatile("cp.async.commit_group;" ::: "memory")
#define CP_WAIT(n)  asm volatile("cp.async.wait_group %0;" :: "n"(n) : "memory")

__device__ __forceinline__ void ldsm4(uint32_t* r, uint32_t addr) {
    asm volatile("ldmatrix.sync.aligned.m8n8.x4.shared.b16 {%0,%1,%2,%3}, [%4];"
        : "=r"(r[0]), "=r"(r[1]), "=r"(r[2]), "=r"(r[3]) : "r"(addr));
}
__device__ __forceinline__ void mma16816(float* d, const uint32_t* a, const uint32_t* b) {
    asm volatile(
        "mma.sync.aligned.m16n8k16.row.col.f32.bf16.bf16.f32 "
        "{%0,%1,%2,%3}, {%4,%5,%6,%7}, {%8,%9}, {%0,%1,%2,%3};"
        : "+f"(d[0]), "+f"(d[1]), "+f"(d[2]), "+f"(d[3])
        : "r"(a[0]), "r"(a[1]), "r"(a[2]), "r"(a[3]), "r"(b[0]), "r"(b[1]));
}

// ---------------- math helpers ----------------
__device__ __forceinline__ float sigmoidf_(float x) { return 1.0f / (1.0f + expf(-x)); }
__device__ __forceinline__ float softplusf_(float x) {
    return fmaxf(x, 0.0f) + log1pf(expf(-fabsf(x)));
}

// ---------------- fp32 -> bf16 hi/lo splits ----------------
__global__ __launch_bounds__(256)
void split_bf16(const float* __restrict__ src, __nv_bfloat16* __restrict__ hi,
                __nv_bfloat16* __restrict__ lo)
{
    size_t i = (size_t)blockIdx.x * 256 + threadIdx.x;
    float v = src[i];
    __nv_bfloat16 h = __float2bfloat16(v);
    hi[i] = h;
    lo[i] = __float2bfloat16(v - __bfloat162float(h));
}

__global__ __launch_bounds__(256)
void split_wres(const float* __restrict__ W)
{
    size_t i = (size_t)blockIdx.x * 256 + threadIdx.x;   // 0..1024*1024-1
    int d = (int)(i >> 10);
    int k = (int)(i & 1023);
    float v = (k < 1022) ? W[(size_t)d * 1022 + k] : 0.0f;
    __nv_bfloat16 h = __float2bfloat16(v);
    g_wrh[i] = h;
    g_wrl[i] = __float2bfloat16(v - __bfloat162float(h));
}

// ---------------- mma.sync GEMM: C = sc*((Ahi+Alo)(Bhi+Blo)^T + bias) --------
// A: [M,1024] bf16 K-major; B: [Ntot,1024] bf16 K-major.
// CTA tile 128x128, BK=32, 8 warps (4 over M x 2 over N), warp tile 32x64.
#define GBK 32
#define NKC (D_MODEL / GBK)           // 32 chunks
#define STG_A_HI 0
#define STG_A_LO 8192
#define STG_B_HI 16384
#define STG_B_LO 24576
#define STG_BYTES 32768

// smem tile layout: [128 rows][4 chunks of 16B], chunk swizzle c ^ ((row>>1)&3)
__device__ __forceinline__ uint32_t tile_off(int row, int k16) {
    return (uint32_t)(row * 64 + ((k16 ^ ((row >> 1) & 3)) << 4));
}

__device__ __forceinline__ void load_chunk(
    uint32_t sdst,
    const __nv_bfloat16* __restrict__ Ahi, const __nv_bfloat16* __restrict__ Alo,
    const __nv_bfloat16* __restrict__ Bhi, const __nv_bfloat16* __restrict__ Blo,
    int m0, int n0, int kc, int tid)
{
    const __nv_bfloat16* srcs[4] = { Ahi, Alo, Bhi, Blo };
    const int bases[4] = { m0, m0, n0, n0 };
    const uint32_t offs[4] = { STG_A_HI, STG_A_LO, STG_B_HI, STG_B_LO };
    #pragma unroll
    for (int a = 0; a < 4; a++) {
        #pragma unroll
        for (int rep = 0; rep < 2; rep++) {
            int c = tid + rep * 256;          // 0..511
            int row = c >> 2;
            int k16 = c & 3;
            const __nv_bfloat16* g = srcs[a]
                + (size_t)(bases[a] + row) * D_MODEL + kc * GBK + k16 * 8;
            cpasync16(sdst + offs[a] + tile_off(row, k16), g);
        }
    }
}

__global__ __launch_bounds__(256, 1)
void gemm_mma(const __nv_bfloat16* __restrict__ Ahi, const __nv_bfloat16* __restrict__ Alo,
              const __nv_bfloat16* __restrict__ Bhi, const __nv_bfloat16* __restrict__ Blo,
              float* __restrict__ C, const float* __restrict__ bias,
              const float* __restrict__ scale_ptr, int Ntot)
{
    extern __shared__ __align__(1024) char smem[];
    __shared__ float s_bias[128];

    const int tid = threadIdx.x;
    const int wid = tid >> 5, l = tid & 31;
    const int warp_m = wid & 3;        // 0..3, 32 rows each
    const int warp_n = wid >> 2;       // 0..1, 64 cols each
    const int m0 = blockIdx.y * 128;
    const int n0 = blockIdx.x * 128;
    const uint32_t sb = smem_u32(smem);

    if (tid < 128) s_bias[tid] = bias ? bias[n0 + tid] : 0.0f;

    float acc[2][8][4];
    #pragma unroll
    for (int mi = 0; mi < 2; mi++)
        #pragma unroll
        for (int ni = 0; ni < 8; ni++)
            #pragma unroll
            for (int e = 0; e < 4; e++) acc[mi][ni][e] = 0.0f;

    // A ldmatrix lane address: row = warp_m*32 + mi*16 + (l&15), k16 = ks*2 + (l>>4)
    const int a_row_l = (l & 15);
    const int a_k_l   = (l >> 4);
    // B: row = warp_n*64 + pi*16 + ((l>>4)&1)*8 + (l&7), k16 = ks*2 + ((l>>3)&1)
    const int b_row_l = ((l >> 4) & 1) * 8 + (l & 7);
    const int b_k_l   = ((l >> 3) & 1);

    load_chunk(sb, Ahi, Alo, Bhi, Blo, m0, n0, 0, tid);
    CP_COMMIT();

    #pragma unroll 1
    for (int kc = 0; kc < NKC; kc++) {
        const uint32_t st = sb + (uint32_t)(kc & 1) * STG_BYTES;
        if (kc + 1 < NKC) {
            load_chunk(sb + (uint32_t)((kc + 1) & 1) * STG_BYTES,
                       Ahi, Alo, Bhi, Blo, m0, n0, kc + 1, tid);
            CP_COMMIT();
            CP_WAIT(1);
        } else {
            CP_WAIT(0);
        }
        __syncthreads();

        #pragma unroll
        for (int ks = 0; ks < 2; ks++) {
            uint32_t ah[2][4], al[2][4], bh[4][4], bl[4][4];
            #pragma unroll
            for (int mi = 0; mi < 2; mi++) {
                int row = warp_m * 32 + mi * 16 + a_row_l;
                int k16 = ks * 2 + a_k_l;
                ldsm4(ah[mi], st + STG_A_HI + tile_off(row, k16));
                ldsm4(al[mi], st + STG_A_LO + tile_off(row, k16));
            }
            #pragma unroll
            for (int pi = 0; pi < 4; pi++) {
                int row = warp_n * 64 + pi * 16 + b_row_l;
                int k16 = ks * 2 + b_k_l;
                ldsm4(bh[pi], st + STG_B_HI + tile_off(row, k16));
                ldsm4(bl[pi], st + STG_B_LO + tile_off(row, k16));
            }
            #pragma unroll
            for (int mi = 0; mi < 2; mi++)
                #pragma unroll
                for (int pi = 0; pi < 4; pi++) {
                    #pragma unroll
                    for (int h = 0; h < 2; h++) {
                        int ni = pi * 2 + h;
                        mma16816(acc[mi][ni], ah[mi], &bh[pi][h * 2]);
                        mma16816(acc[mi][ni], ah[mi], &bl[pi][h * 2]);
                        mma16816(acc[mi][ni], al[mi], &bh[pi][h * 2]);
                    }
                }
        }
        __syncthreads();
    }

    const float sc = scale_ptr ? *scale_ptr : 1.0f;
    #pragma unroll
    for (int mi = 0; mi < 2; mi++) {
        #pragma unroll
        for (int ni = 0; ni < 8; ni++) {
            int r = m0 + warp_m * 32 + mi * 16 + (l >> 2);
            int cb = warp_n * 64 + ni * 8 + (l & 3) * 2;
            int cg = n0 + cb;
            float2 v0, v1;
            v0.x = (acc[mi][ni][0] + s_bias[cb + 0]) * sc;
            v0.y = (acc[mi][ni][1] + s_bias[cb + 1]) * sc;
            v1.x = (acc[mi][ni][2] + s_bias[cb + 0]) * sc;
            v1.y = (acc[mi][ni][3] + s_bias[cb + 1]) * sc;
            *reinterpret_cast<float2*>(&C[(size_t)r * Ntot + cg]) = v0;
            *reinterpret_cast<float2*>(&C[(size_t)(r + 8) * Ntot + cg]) = v1;
        }
    }
}

// ---------------- scan stage 1 ----------------
__global__ __launch_bounds__(KOSC)
void scan_partial()
{
    const int b = blockIdx.y;
    const int tile = blockIdx.x;
    const int k = threadIdx.x;
    float aP = 1.0f, bR = 0.0f, bI = 0.0f;
    const int nbase = tile * TILE_N;

    for (int i = 0; i < TILE_N; i++) {
        int n = nbase + i;
        size_t base = (size_t)(b * SEQ + n) * NPROJ;
        float a_raw  = g_proj[base + k];
        float w_raw  = g_proj[base + KOSC + k];
        float p_raw  = g_proj[base + 2 * KOSC + k];
        float al_raw = g_proj[base + 3 * KOSC + k];

        float alpha = sigmoidf_(al_raw);
        float Aamp  = 3.0f * sigmoidf_(a_raw);
        float omega = softplusf_(w_raw);
        float lp    = log1pf((float)n);
        float s, c;
        sincosf(fmaf(omega, lp, p_raw), &s, &c);
        float oma = 1.0f - alpha;
        bR = fmaf(alpha, bR, oma * Aamp * c);
        bI = fmaf(alpha, bI, oma * Aamp * s);
        aP *= alpha;
    }
    int idx = (b * NTILES + tile) * KOSC + k;
    g_tA[idx] = aP; g_tBr[idx] = bR; g_tBi[idx] = bI;
}

// ---------------- scan stage 2 ----------------
__global__ __launch_bounds__(KOSC)
void scan_prefix()
{
    const int b = blockIdx.x;
    const int k = threadIdx.x;
    float rr = 0.0f, ri = 0.0f;
    for (int t = 0; t < NTILES; t += 4) {
        int i0 = (b * NTILES + t) * KOSC + k;
        float a0 = g_tA[i0],          br0 = g_tBr[i0],          bi0 = g_tBi[i0];
        float a1 = g_tA[i0+KOSC],     br1 = g_tBr[i0+KOSC],     bi1 = g_tBi[i0+KOSC];
        float a2 = g_tA[i0+2*KOSC],   br2 = g_tBr[i0+2*KOSC],   bi2 = g_tBi[i0+2*KOSC];
        float a3 = g_tA[i0+3*KOSC],   br3 = g_tBr[i0+3*KOSC],   bi3 = g_tBi[i0+3*KOSC];
        g_pR[i0] = rr;          g_pI[i0] = ri;
        rr = fmaf(a0, rr, br0); ri = fmaf(a0, ri, bi0);
        g_pR[i0+KOSC] = rr;     g_pI[i0+KOSC] = ri;
        rr = fmaf(a1, rr, br1); ri = fmaf(a1, ri, bi1);
        g_pR[i0+2*KOSC] = rr;   g_pI[i0+2*KOSC] = ri;
        rr = fmaf(a2, rr, br2); ri = fmaf(a2, ri, bi2);
        g_pR[i0+3*KOSC] = rr;   g_pI[i0+3*KOSC] = ri;
        rr = fmaf(a3, rr, br3); ri = fmaf(a3, ri, bi3);
    }
}

// ---------------- scan stage 3: tail, writes rho bf16 hi/lo ------------------
__global__ __launch_bounds__(KOSC)
void scan_final(const float* __restrict__ lambda_ptr)
{
    __shared__ float s_re[KOSC], s_im[KOSC], s_g[KOSC];
    const int b = blockIdx.y;
    const int tile = blockIdx.x;
    const int k = threadIdx.x;
    const float lam = *lambda_ptr;

    int idx = (b * NTILES + tile) * KOSC + k;
    float rr = g_pR[idx], ri = g_pI[idx];
    const int nbase = tile * TILE_N;

    for (int i = 0; i < TILE_N; i++) {
        int n = nbase + i;
        size_t row = (size_t)(b * SEQ + n);
        size_t base = row * NPROJ;
        float a_raw  = g_proj[base + k];
        float w_raw  = g_proj[base + KOSC + k];
        float p_raw  = g_proj[base + 2 * KOSC + k];
        float al_raw = g_proj[base + 3 * KOSC + k];
        float g_raw  = g_proj[base + 4 * KOSC + k];
        float be_raw = g_proj[base + 5 * KOSC + k];

        float alpha = sigmoidf_(al_raw);
        float Aamp  = 3.0f * sigmoidf_(a_raw);
        float omega = softplusf_(w_raw);
        float g     = sigmoidf_(g_raw);
        float beta  = sigmoidf_(be_raw);
        float lp    = log1pf((float)n);
        float s, c;
        sincosf(fmaf(omega, lp, p_raw), &s, &c);

        float oma = 1.0f - alpha;
        rr = fmaf(alpha, rr, oma * Aamp * c);
        ri = fmaf(alpha, ri, oma * Aamp * s);

        float readout = rr * c + ri * s;
        float er = rr - beta * readout * c;
        float ei = ri - beta * readout * s;

        float mod = sqrtf(er * er + ei * ei + 1e-8f);
        float inv = 1.0f / fmaxf(mod, 1.0f);
        er *= inv; ei *= inv;

        float re =  er * c + ei * s;
        float im = -er * s + ei * c;

        float rn = sqrtf(re * re + im * im + 1e-8f);
        float pq = g_pq[row * KOSC + k];
        float sq, cq;
        sincosf(pq, &sq, &cq);
        float align = (re * cq + im * sq) / rn;
        float gate = sigmoidf_(lam * align);
        re *= gate; im *= gate;

        s_re[k] = re; s_im[k] = im; s_g[k] = g;
        __syncthreads();

        size_t ob = row * NRHO;
        float v0 = g * re;
        float v1 = g * im;
        __nv_bfloat16 h0 = __float2bfloat16(v0);
        __nv_bfloat16 h1 = __float2bfloat16(v1);
        g_rhoh[ob + k]        = h0;
        g_rhol[ob + k]        = __float2bfloat16(v0 - __bfloat162float(h0));
        g_rhoh[ob + KOSC + k] = h1;
        g_rhol[ob + KOSC + k] = __float2bfloat16(v1 - __bfloat162float(h1));
        if (k < KOSC - 1) {
            float re2 = s_re[k + 1], im2 = s_im[k + 1], g2 = s_g[k + 1];
            float xr = re * re2 - im * im2;
            float xi = re * im2 + im * re2;
            float gc = 0.5f * (g + g2);
            float w0 = gc * xr, w1 = gc * xi;
            __nv_bfloat16 hh0 = __float2bfloat16(w0);
            __nv_bfloat16 hh1 = __float2bfloat16(w1);
            g_rhoh[ob + 2 * KOSC + k]              = hh0;
            g_rhol[ob + 2 * KOSC + k]              = __float2bfloat16(w0 - __bfloat162float(hh0));
            g_rhoh[ob + 2 * KOSC + (KOSC - 1) + k] = hh1;
            g_rhol[ob + 2 * KOSC + (KOSC - 1) + k] = __float2bfloat16(w1 - __bfloat162float(hh1));
        } else {
            __nv_bfloat16 z = __float2bfloat16(0.0f);
            g_rhoh[ob + 1022] = z; g_rhol[ob + 1022] = z;
            g_rhoh[ob + 1023] = z; g_rhol[ob + 1023] = z;
        }
        __syncthreads();
    }
}

// ---------------- launch ----------------
extern "C" void kernel_launch(void* const* d_in, const int* in_sizes, int n_in,
                              void* d_out, int out_size)
{
    const float* x        = (const float*)d_in[0];
    const float* W_proj   = (const float*)d_in[1];
    const float* b_proj   = (const float*)d_in[2];
    const float* W_res    = (const float*)d_in[3];
    const float* W_phase  = (const float*)d_in[4];
    const float* b_phase  = (const float*)d_in[5];
    const float* lambda_p = (const float*)d_in[6];
    const float* res_p    = (const float*)d_in[7];
    float* out = (float*)d_out;

    float *proj, *pq;
    __nv_bfloat16 *xhi, *xlo, *wph, *wpl, *wqh, *wql, *wrh, *wrl, *rhoh, *rhol;
    cudaGetSymbolAddress((void**)&proj, g_proj);
    cudaGetSymbolAddress((void**)&pq,   g_pq);
    cudaGetSymbolAddress((void**)&xhi,  g_xhi);
    cudaGetSymbolAddress((void**)&xlo,  g_xlo);
    cudaGetSymbolAddress((void**)&wph,  g_wph);
    cudaGetSymbolAddress((void**)&wpl,  g_wpl);
    cudaGetSymbolAddress((void**)&wqh,  g_wqh);
    cudaGetSymbolAddress((void**)&wql,  g_wql);
    cudaGetSymbolAddress((void**)&wrh,  g_wrh);
    cudaGetSymbolAddress((void**)&wrl,  g_wrl);
    cudaGetSymbolAddress((void**)&rhoh, g_rhoh);
    cudaGetSymbolAddress((void**)&rhol, g_rhol);

    const int DYN = 2 * STG_BYTES;   // 64 KB
    cudaFuncSetAttribute(gemm_mma, cudaFuncAttributeMaxDynamicSharedMemorySize, DYN);

    split_bf16<<<(M_TOT * D_MODEL) / 256, 256>>>(x, xhi, xlo);
    split_bf16<<<(NPROJ * D_MODEL) / 256, 256>>>(W_proj, wph, wpl);
    split_bf16<<<(KOSC * D_MODEL) / 256, 256>>>(W_phase, wqh, wql);
    split_wres<<<(1024 * 1024) / 256, 256>>>(W_res);

    // GEMM1a: proj = x @ W_proj^T + b_proj   (16384 x 1536 x 1024)
    gemm_mma<<<dim3(NPROJ / 128, M_TOT / 128), 256, DYN>>>(
        xhi, xlo, wph, wpl, proj, b_proj, nullptr, NPROJ);
    // GEMM1b: pq = x @ W_phase^T + b_phase   (16384 x 256 x 1024)
    gemm_mma<<<dim3(KOSC / 128, M_TOT / 128), 256, DYN>>>(
        xhi, xlo, wqh, wql, pq, b_phase, nullptr, KOSC);

    scan_partial<<<dim3(NTILES, BATCH), KOSC>>>();
    scan_prefix<<<BATCH, KOSC>>>();
    scan_final<<<dim3(NTILES, BATCH), KOSC>>>(lambda_p);

    // GEMM2: out = res_scale * rho @ Wres^T   (16384 x 1024 x 1024)
    gemm_mma<<<dim3(NRHO / 128, M_TOT / 128), 256, DYN>>>(
        rhoh, rhol, wrh, wrl, out, nullptr, res_p, NRHO);
}